// round 12
// baseline (speedup 1.0000x reference)
#include <cuda_runtime.h>
#include <cuda_fp16.h>
#include <cstdint>

// MultiLayerDeepSNN: 15-step LIF SNN, B=16384, layers 6->256->256->256->256->128->3.
// Round 12: persistent kernel restructured to 2 CTAs/SM (64 rows each, 256 thr,
// 8 warps) so barriers/epilogue/L2 waits of one CTA overlap the other's HMMA.
// W streamed in BK=32 stages (double-buffered); cross-tile stage-0 prefetch kept.
// hi/lo MMAs issued as two independent 8-wide groups.

#define NB 16384
#define THRV 1.0f

#define AT_H  (64 * 40)          // A chunk: 64 rows x 40 halfs (5120 B)
#define WT_H  (128 * 40)         // W chunk: 128 rows x 40 halfs (10240 B)
#define SA_H  (8 * AT_H)         // A buffer: 8 chunks = 64x256 (40960 B)
#define SWB_H (2 * WT_H)         // one BK=32 W stage: hi+lo (20480 B)
#define SW_H  (2 * SWB_H)        // double buffered (40960 B)
#define SMEMT ((SA_H + SW_H) * 2 + 1536)   // + W6 = 83456 B -> 2 CTAs/SM

// ---------------- scratch -------------------------------------------------
__device__ __half g_spk1[15 * NB * 256];
__device__ float g_mem2[NB * 256];
__device__ float g_mem3[NB * 256];
__device__ float g_mem4[NB * 256];
__device__ float g_mem5[NB * 128];
__device__ __half g_Wh[3 * 65536 + 32768];
__device__ __half g_Wl[3 * 65536 + 32768];

// ---------------- helpers -------------------------------------------------
__device__ __forceinline__ unsigned int s2u(const void* p) {
    return (unsigned int)__cvta_generic_to_shared(p);
}
__device__ __forceinline__ void cp16(void* dst, const void* src) {
    asm volatile("cp.async.cg.shared.global [%0], [%1], 16;"
                 :: "r"(s2u(dst)), "l"(src));
}
__device__ __forceinline__ void ldmx4(unsigned int& r0, unsigned int& r1,
                                      unsigned int& r2, unsigned int& r3,
                                      unsigned int addr) {
    asm volatile("ldmatrix.sync.aligned.m8n8.x4.shared.b16 {%0,%1,%2,%3}, [%4];"
                 : "=r"(r0), "=r"(r1), "=r"(r2), "=r"(r3) : "r"(addr));
}
__device__ __forceinline__ void mma16816(float* c, const unsigned int* a,
                                         const unsigned int* b) {
    asm volatile(
        "mma.sync.aligned.m16n8k16.row.col.f32.f16.f16.f32 "
        "{%0,%1,%2,%3},{%4,%5,%6,%7},{%8,%9},{%0,%1,%2,%3};"
        : "+f"(c[0]), "+f"(c[1]), "+f"(c[2]), "+f"(c[3])
        : "r"(a[0]), "r"(a[1]), "r"(a[2]), "r"(a[3]), "r"(b[0]), "r"(b[1]));
}

// W stage loader: stage s covers K [s*32, s*32+32) (one 32-col chunk, hi+lo).
// 512 segment-tasks, each a cp16 PAIR. Audit: 512*16 = 8192 halfs = 2*128*32.
__device__ __forceinline__ void stage_load(__half* dbuf, const __half* Hg,
                                           const __half* Lg, int s, int tid) {
#pragma unroll
    for (int i = 0; i < 2; i++) {
        int id = i * 256 + tid;
        int hl = (id >> 8) & 1;
        int rr = (id >> 1) & 127;
        int sg = (id & 1) * 16;
        const __half* src = (hl ? Lg : Hg) + (size_t)rr * 256 + s * 32 + sg;
        __half* dst = dbuf + hl * WT_H + rr * 40 + sg;
        cp16(dst, src);
        cp16(dst + 8, src + 8);
    }
    asm volatile("cp.async.commit_group;");
}

// ---------------- merged setup: zero mems + split weights + layer1 chain ---
__global__ void k_setup(const float* __restrict__ x, const float* __restrict__ W1,
                        const float* __restrict__ b1,
                        const float* __restrict__ W2, const float* __restrict__ W3,
                        const float* __restrict__ W4, const float* __restrict__ W5) {
    int idx = blockIdx.x * blockDim.x + threadIdx.x;
    int stride = gridDim.x * blockDim.x;
    for (int i = idx; i < NB * 256; i += stride) {
        g_mem2[i] = 0.f; g_mem3[i] = 0.f; g_mem4[i] = 0.f;
    }
    for (int i = idx; i < NB * 128; i += stride) g_mem5[i] = 0.f;

    for (int i = idx; i < 65536; i += stride) {
        float w = W2[i]; __half h = __float2half_rn(w);
        g_Wh[i] = h; g_Wl[i] = __float2half_rn(w - __half2float(h));
        w = W3[i]; h = __float2half_rn(w);
        g_Wh[65536 + i] = h; g_Wl[65536 + i] = __float2half_rn(w - __half2float(h));
        w = W4[i]; h = __float2half_rn(w);
        g_Wh[131072 + i] = h; g_Wl[131072 + i] = __float2half_rn(w - __half2float(h));
    }
    for (int i = idx; i < 32768; i += stride) {
        float w = W5[i]; __half h = __float2half_rn(w);
        g_Wh[196608 + i] = h; g_Wl[196608 + i] = __float2half_rn(w - __half2float(h));
    }

    for (int i = idx; i < NB * 256; i += stride) {
        int b = i >> 8, o = i & 255;
        const float* xr = x + b * 6;
        const float* wr = W1 + o * 6;
        float cur = __ldg(b1 + o);
#pragma unroll
        for (int j = 0; j < 6; j++) cur = fmaf(__ldg(xr + j), __ldg(wr + j), cur);
        float m = 0.f;
#pragma unroll
        for (int t = 0; t < 15; t++) {
            float r = (m > THRV) ? THRV : 0.f;
            m = 0.90f * m + cur - r;
            g_spk1[t * (NB * 256) + i] = __float2half_rn(m > THRV ? 1.f : 0.f);
        }
    }
}

// ---------------- GEMM: A (64x256) resident, W streamed in BK=32 stages ----
// 8 warps (2m x 4n), warp tile 32x32, acc[2][4][4]. hi then lo issue groups.
__device__ __forceinline__ void gemm8(
    const __half* sA, __half* sW,
    const __half* __restrict__ Hg, const __half* __restrict__ Lg,
    const __half* nH, const __half* nL, int pre,
    int tid, int lane, int wm, int wn, float acc[2][4][4]) {
    const int aRowL = (lane & 15);
    const int aColL = (lane >> 4) * 8;
    const int bRowL = (lane & 7) + ((lane >> 4) & 1) * 8;
    const int bColL = ((lane >> 3) & 1) * 8;

    if (!pre) stage_load(sW, Hg, Lg, 0, tid);

#pragma unroll 1
    for (int s = 0; s < 8; s++) {
        asm volatile("cp.async.wait_group 0;");
        __syncthreads();                       // buf(s&1) visible; other free
        if (s < 7) {
            stage_load(sW + ((s + 1) & 1) * SWB_H, Hg, Lg, s + 1, tid);
        } else if (nH) {
            stage_load(sW + ((s + 1) & 1) * SWB_H, nH, nL, 0, tid);
        }

        const __half* cA = sA + s * AT_H;
        const __half* sH = sW + (s & 1) * SWB_H;
        const __half* sL = sH + WT_H;

#pragma unroll
        for (int kk = 0; kk < 2; kk++) {
            unsigned int aF[2][4];
#pragma unroll
            for (int mt = 0; mt < 2; mt++) {
                unsigned int ad =
                    s2u(cA + (wm * 32 + mt * 16 + aRowL) * 40 + kk * 16 + aColL);
                ldmx4(aF[mt][0], aF[mt][1], aF[mt][2], aF[mt][3], ad);
            }
            unsigned int hF[4][2], lF[4][2];
#pragma unroll
            for (int p = 0; p < 2; p++) {
                unsigned int r0, r1, r2, r3;
                unsigned int bd =
                    s2u(sH + (wn * 32 + p * 16 + bRowL) * 40 + kk * 16 + bColL);
                ldmx4(r0, r1, r2, r3, bd);
                hF[2 * p][0] = r0; hF[2 * p][1] = r1;
                hF[2 * p + 1][0] = r2; hF[2 * p + 1][1] = r3;
                unsigned int ld =
                    s2u(sL + (wn * 32 + p * 16 + bRowL) * 40 + kk * 16 + bColL);
                ldmx4(r0, r1, r2, r3, ld);
                lF[2 * p][0] = r0; lF[2 * p][1] = r1;
                lF[2 * p + 1][0] = r2; lF[2 * p + 1][1] = r3;
            }
            // 8 independent hi MMAs, then 8 lo (each lo depends only on its hi)
#pragma unroll
            for (int mt = 0; mt < 2; mt++)
#pragma unroll
                for (int nt = 0; nt < 4; nt++)
                    mma16816(acc[mt][nt], aF[mt], hF[nt]);
#pragma unroll
            for (int mt = 0; mt < 2; mt++)
#pragma unroll
                for (int nt = 0; nt < 4; nt++)
                    mma16816(acc[mt][nt], aF[mt], lF[nt]);
        }
    }
    __syncthreads();   // all warps done reading sA/sW before epilogue writes sA
}

// ---------------- the persistent SNN kernel --------------------------------
__global__ __launch_bounds__(256, 2) void k_snn(
    const __half* __restrict__ spk1, const __half* __restrict__ Wh,
    const __half* __restrict__ Wl,
    const float* __restrict__ b2, const float* __restrict__ b3,
    const float* __restrict__ b4, const float* __restrict__ b5,
    float* __restrict__ mem2, float* __restrict__ mem3,
    float* __restrict__ mem4, float* __restrict__ mem5,
    const float* __restrict__ W6, const float* __restrict__ b6,
    float* __restrict__ out) {
    extern __shared__ __half smbuf[];
    __half* sA = smbuf;
    __half* sW = smbuf + SA_H;
    float* ws = (float*)(smbuf + SA_H + SW_H);

    const int tid = threadIdx.x;
    const int lane = tid & 31, wid = tid >> 5;
    const int wm = wid >> 2, wn = wid & 3;     // 2m x 4n warps
    const int m0 = blockIdx.x * 64;

    for (int i = tid; i < 384; i += 256) ws[i] = W6[i];

    const int rowL = wm * 32 + (lane >> 2);
    const int colL = wn * 32 + (lane & 3) * 2;

    float o0 = 0.f, o1 = 0.f, o2 = 0.f;
    const float b60 = __ldg(b6 + 0), b61 = __ldg(b6 + 1), b62 = __ldg(b6 + 2);

    const __half* WhL[4] = {Wh, Wh + 65536, Wh + 131072, Wh + 196608};
    const __half* WlL[4] = {Wl, Wl + 65536, Wl + 131072, Wl + 196608};
    const float* biasL[3] = {b2, b3, b4};
    float* memL[3] = {mem2, mem3, mem4};
    const float betaL[3] = {0.88f, 0.86f, 0.84f};

    int pre = 0;

#pragma unroll 1
    for (int t = 0; t < 15; ++t) {
        // ---- stage layer-1 spikes (64 rows x 256) into sA chunk layout ----
        // 1024 tasks (8 chunks x 64 rows x 2 segs), cp16 PAIR each.
        // Audit: 1024*16 = 16384 halfs = 64*256.
        {
            const __half* Ag = spk1 + ((size_t)t * NB + m0) * 256;
#pragma unroll
            for (int i = 0; i < 4; i++) {
                int id = i * 256 + tid;
                int c = id >> 7;
                int rr = (id >> 1) & 63;
                int sg = (id & 1) * 16;
                __half* dst = sA + c * AT_H + rr * 40 + sg;
                const __half* src = Ag + rr * 256 + c * 32 + sg;
                cp16(dst, src);
                cp16(dst + 8, src + 8);
            }
            asm volatile("cp.async.commit_group;");
        }

        // ---- layers 2..4 (N=256: two 128-col tiles) -----------------------
#pragma unroll 1
        for (int l = 0; l < 3; l++) {
            const float beta = betaL[l];
            float* mem = memL[l];
            const float* bias = biasL[l];
            __half2 s0v[2][4][2];   // tile-0 spikes parked in regs

#pragma unroll 1
            for (int ht = 0; ht < 2; ht++) {
                const __half *nH, *nL;
                if (ht == 0) { nH = WhL[l] + 128 * 256; nL = WlL[l] + 128 * 256; }
                else if (l < 2) { nH = WhL[l + 1]; nL = WlL[l + 1]; }
                else { nH = WhL[3]; nL = WlL[3]; }

                float acc[2][4][4];
#pragma unroll
                for (int i = 0; i < 2; i++)
#pragma unroll
                    for (int j = 0; j < 4; j++)
#pragma unroll
                        for (int q = 0; q < 4; q++) acc[i][j][q] = 0.f;

                gemm8(sA, sW, WhL[l] + ht * 128 * 256, WlL[l] + ht * 128 * 256,
                      nH, nL, pre, tid, lane, wm, wn, acc);
                pre = 1;

#pragma unroll
                for (int mt = 0; mt < 2; mt++) {
                    int rl = rowL + mt * 16;
                    int r = m0 + rl;
#pragma unroll
                    for (int nt = 0; nt < 4; nt++) {
                        int c = ht * 128 + colL + nt * 8;
                        size_t gi0 = (size_t)r * 256 + c;
                        size_t gi1 = gi0 + (size_t)8 * 256;
                        float2 bb = *(const float2*)(bias + c);
                        float2 mp0 = *(float2*)(mem + gi0);
                        float2 mp1 = *(float2*)(mem + gi1);
                        float cv0 = acc[mt][nt][0] + bb.x;
                        float cv1 = acc[mt][nt][1] + bb.y;
                        float cv2 = acc[mt][nt][2] + bb.x;
                        float cv3 = acc[mt][nt][3] + bb.y;
                        float n0v = beta * mp0.x + cv0 - (mp0.x > THRV ? THRV : 0.f);
                        float n1v = beta * mp0.y + cv1 - (mp0.y > THRV ? THRV : 0.f);
                        float n2v = beta * mp1.x + cv2 - (mp1.x > THRV ? THRV : 0.f);
                        float n3v = beta * mp1.y + cv3 - (mp1.y > THRV ? THRV : 0.f);
                        *(float2*)(mem + gi0) = make_float2(n0v, n1v);
                        *(float2*)(mem + gi1) = make_float2(n2v, n3v);
                        __half2 p0 = __floats2half2_rn(n0v > THRV ? 1.f : 0.f,
                                                       n1v > THRV ? 1.f : 0.f);
                        __half2 p1 = __floats2half2_rn(n2v > THRV ? 1.f : 0.f,
                                                       n3v > THRV ? 1.f : 0.f);
                        if (ht == 0) {
                            s0v[mt][nt][0] = p0;
                            s0v[mt][nt][1] = p1;
                        } else {
                            int cc = c & 31;
                            __half* base = sA + (c >> 5) * AT_H;
                            *(__half2*)(base + rl * 40 + cc) = p0;
                            *(__half2*)(base + (rl + 8) * 40 + cc) = p1;
                        }
                    }
                }
            }
            // park tile-0 spikes into sA
#pragma unroll
            for (int mt = 0; mt < 2; mt++) {
                int rl = rowL + mt * 16;
#pragma unroll
                for (int nt = 0; nt < 4; nt++) {
                    int c = colL + nt * 8;
                    int cc = c & 31;
                    __half* base = sA + (c >> 5) * AT_H;
                    *(__half2*)(base + rl * 40 + cc) = s0v[mt][nt][0];
                    *(__half2*)(base + (rl + 8) * 40 + cc) = s0v[mt][nt][1];
                }
            }
            __syncthreads();
        }

        // ---- layer 5 (N=128) + fused output head --------------------------
        {
            const __half* nH = (t < 14) ? WhL[0] : nullptr;
            const __half* nL = (t < 14) ? WlL[0] : nullptr;

            float acc[2][4][4];
#pragma unroll
            for (int i = 0; i < 2; i++)
#pragma unroll
                for (int j = 0; j < 4; j++)
#pragma unroll
                    for (int q = 0; q < 4; q++) acc[i][j][q] = 0.f;

            gemm8(sA, sW, WhL[3], WlL[3], nH, nL, pre, tid, lane, wm, wn, acc);

#pragma unroll
            for (int mt = 0; mt < 2; mt++) {
                int rl = rowL + mt * 16;
                int r = m0 + rl;
#pragma unroll
                for (int nt = 0; nt < 4; nt++) {
                    int c = colL + nt * 8;
                    size_t gi0 = (size_t)r * 128 + c;
                    size_t gi1 = gi0 + (size_t)8 * 128;
                    float2 bb = *(const float2*)(b5 + c);
                    float2 mp0 = *(float2*)(mem5 + gi0);
                    float2 mp1 = *(float2*)(mem5 + gi1);
                    float cv0 = acc[mt][nt][0] + bb.x;
                    float cv1 = acc[mt][nt][1] + bb.y;
                    float cv2 = acc[mt][nt][2] + bb.x;
                    float cv3 = acc[mt][nt][3] + bb.y;
                    float n0v = 0.82f * mp0.x + cv0 - (mp0.x > THRV ? THRV : 0.f);
                    float n1v = 0.82f * mp0.y + cv1 - (mp0.y > THRV ? THRV : 0.f);
                    float n2v = 0.82f * mp1.x + cv2 - (mp1.x > THRV ? THRV : 0.f);
                    float n3v = 0.82f * mp1.y + cv3 - (mp1.y > THRV ? THRV : 0.f);
                    *(float2*)(mem5 + gi0) = make_float2(n0v, n1v);
                    *(float2*)(mem5 + gi1) = make_float2(n2v, n3v);
                    int cc = c & 31;
                    __half* base = sA + (c >> 5) * AT_H;
                    *(__half2*)(base + rl * 40 + cc) =
                        __floats2half2_rn(n0v > THRV ? 1.f : 0.f,
                                          n1v > THRV ? 1.f : 0.f);
                    *(__half2*)(base + (rl + 8) * 40 + cc) =
                        __floats2half2_rn(n2v > THRV ? 1.f : 0.f,
                                          n3v > THRV ? 1.f : 0.f);
                }
            }
            __syncthreads();

            if (tid < 64) {
                float s0 = b60, s1 = b61, s2v = b62;
#pragma unroll
                for (int ch = 0; ch < 4; ch++) {
                    const __half* sr = sA + ch * AT_H + tid * 40;
#pragma unroll
                    for (int k = 0; k < 32; k++) {
                        float v = __half2float(sr[k]);
                        int x = ch * 32 + k;
                        s0 = fmaf(v, ws[x], s0);
                        s1 = fmaf(v, ws[128 + x], s1);
                        s2v = fmaf(v, ws[256 + x], s2v);
                    }
                }
                o0 += s0; o1 += s1; o2 += s2v;
            }
            __syncthreads();   // head done before next step's A staging
        }
    }

    if (tid < 64) {
        int b = m0 + tid;
        const float inv = 1.f / 15.f;
        out[b * 3 + 0] = o0 * inv;
        out[b * 3 + 1] = o1 * inv;
        out[b * 3 + 2] = o2 * inv;
    }
}

// ---------------- launch --------------------------------------------------
extern "C" void kernel_launch(void* const* d_in, const int* in_sizes, int n_in,
                              void* d_out, int out_size) {
    const float* x  = (const float*)d_in[0];
    const float* W1 = (const float*)d_in[1];
    const float* b1 = (const float*)d_in[2];
    const float* W2 = (const float*)d_in[3];
    const float* b2 = (const float*)d_in[4];
    const float* W3 = (const float*)d_in[5];
    const float* b3 = (const float*)d_in[6];
    const float* W4 = (const float*)d_in[7];
    const float* b4 = (const float*)d_in[8];
    const float* W5 = (const float*)d_in[9];
    const float* b5 = (const float*)d_in[10];
    const float* W6 = (const float*)d_in[11];
    const float* b6 = (const float*)d_in[12];
    float* out = (float*)d_out;

    __half *p_spk1, *p_Wh, *p_Wl;
    float *p_mem2, *p_mem3, *p_mem4, *p_mem5;
    cudaGetSymbolAddress((void**)&p_spk1, g_spk1);
    cudaGetSymbolAddress((void**)&p_Wh, g_Wh);
    cudaGetSymbolAddress((void**)&p_Wl, g_Wl);
    cudaGetSymbolAddress((void**)&p_mem2, g_mem2);
    cudaGetSymbolAddress((void**)&p_mem3, g_mem3);
    cudaGetSymbolAddress((void**)&p_mem4, g_mem4);
    cudaGetSymbolAddress((void**)&p_mem5, g_mem5);

    cudaFuncSetAttribute(k_snn, cudaFuncAttributeMaxDynamicSharedMemorySize, SMEMT);

    k_setup<<<2048, 256>>>(x, W1, b1, W2, W3, W4, W5);
    k_snn<<<NB / 64, 256, SMEMT>>>(p_spk1, p_Wh, p_Wl, b2, b3, b4, b5,
                                   p_mem2, p_mem3, p_mem4, p_mem5,
                                   W6, b6, out);
}

// round 14
// speedup vs baseline: 1.2515x; 1.2515x over previous
#include <cuda_runtime.h>
#include <cuda_fp16.h>
#include <cstdint>

// MultiLayerDeepSNN: 15-step LIF SNN, B=16384, layers 6->256->256->256->256->128->3.
// Round 14: R13 (mbarrier-ring W pipeline, warps drift, no per-stage syncthreads)
// with the deadlock fixed: cp.async.mbarrier.arrive must be .noinc (the non-noinc
// form self-increments the pending count and never completes an init-count barrier).

#define NB 16384
#define THRV 1.0f

#define T_H   (128 * 40)          // halfs per 32-col chunk (5120)
#define SA_H  (8 * T_H)           // A: 8 chunks = 128x256 halfs (81920 B)
#define SWB_H (4 * T_H)           // one BK=64 W stage: 2 chunks x (hi,lo) (40960 B)
#define NRING 3
#define SW_H  (NRING * SWB_H)     // ring (122880 B)
#define SMEMT ((SA_H + SW_H) * 2 + 64 + 1536)   // + mbars + W6 = 206016 B

// ---------------- scratch -------------------------------------------------
__device__ __half g_spk1[15 * NB * 256];
__device__ float g_mem2[NB * 256];
__device__ float g_mem3[NB * 256];
__device__ float g_mem4[NB * 256];
__device__ float g_mem5[NB * 128];
__device__ __half g_Wh[3 * 65536 + 32768];
__device__ __half g_Wl[3 * 65536 + 32768];

// ---------------- helpers -------------------------------------------------
__device__ __forceinline__ unsigned int s2u(const void* p) {
    return (unsigned int)__cvta_generic_to_shared(p);
}
__device__ __forceinline__ void cp16(void* dst, const void* src) {
    asm volatile("cp.async.cg.shared.global [%0], [%1], 16;"
                 :: "r"(s2u(dst)), "l"(src));
}
__device__ __forceinline__ void ldmx4(unsigned int& r0, unsigned int& r1,
                                      unsigned int& r2, unsigned int& r3,
                                      unsigned int addr) {
    asm volatile("ldmatrix.sync.aligned.m8n8.x4.shared.b16 {%0,%1,%2,%3}, [%4];"
                 : "=r"(r0), "=r"(r1), "=r"(r2), "=r"(r3) : "r"(addr));
}
__device__ __forceinline__ void mma16816(float* c, const unsigned int* a,
                                         const unsigned int* b) {
    asm volatile(
        "mma.sync.aligned.m16n8k16.row.col.f32.f16.f16.f32 "
        "{%0,%1,%2,%3},{%4,%5,%6,%7},{%8,%9},{%0,%1,%2,%3};"
        : "+f"(c[0]), "+f"(c[1]), "+f"(c[2]), "+f"(c[3])
        : "r"(a[0]), "r"(a[1]), "r"(a[2]), "r"(a[3]), "r"(b[0]), "r"(b[1]));
}
__device__ __forceinline__ void mbar_wait(unsigned int addr, unsigned int phase) {
    asm volatile(
        "{\n\t.reg .pred P;\n\tLW_%=:\n\t"
        "mbarrier.try_wait.parity.acquire.cta.shared::cta.b64 P, [%0], %1, 0x989680;\n\t"
        "@P bra LD_%=;\n\tbra LW_%=;\n\tLD_%=:\n\t}"
        :: "r"(addr), "r"(phase) : "memory");
}
__device__ __forceinline__ void mbar_arrive(unsigned int addr) {
    asm volatile("mbarrier.arrive.shared.b64 _, [%0];" :: "r"(addr) : "memory");
}
__device__ __forceinline__ void cpasync_arrive(unsigned int addr) {
    asm volatile("cp.async.mbarrier.arrive.noinc.shared.b64 [%0];"
                 :: "r"(addr) : "memory");
}

// ---------------- merged setup: zero mems + split weights + layer1 chain ---
__global__ void k_setup(const float* __restrict__ x, const float* __restrict__ W1,
                        const float* __restrict__ b1,
                        const float* __restrict__ W2, const float* __restrict__ W3,
                        const float* __restrict__ W4, const float* __restrict__ W5) {
    int idx = blockIdx.x * blockDim.x + threadIdx.x;
    int stride = gridDim.x * blockDim.x;
    for (int i = idx; i < NB * 256; i += stride) {
        g_mem2[i] = 0.f; g_mem3[i] = 0.f; g_mem4[i] = 0.f;
    }
    for (int i = idx; i < NB * 128; i += stride) g_mem5[i] = 0.f;

    for (int i = idx; i < 65536; i += stride) {
        float w = W2[i]; __half h = __float2half_rn(w);
        g_Wh[i] = h; g_Wl[i] = __float2half_rn(w - __half2float(h));
        w = W3[i]; h = __float2half_rn(w);
        g_Wh[65536 + i] = h; g_Wl[65536 + i] = __float2half_rn(w - __half2float(h));
        w = W4[i]; h = __float2half_rn(w);
        g_Wh[131072 + i] = h; g_Wl[131072 + i] = __float2half_rn(w - __half2float(h));
    }
    for (int i = idx; i < 32768; i += stride) {
        float w = W5[i]; __half h = __float2half_rn(w);
        g_Wh[196608 + i] = h; g_Wl[196608 + i] = __float2half_rn(w - __half2float(h));
    }

    for (int i = idx; i < NB * 256; i += stride) {
        int b = i >> 8, o = i & 255;
        const float* xr = x + b * 6;
        const float* wr = W1 + o * 6;
        float cur = __ldg(b1 + o);
#pragma unroll
        for (int j = 0; j < 6; j++) cur = fmaf(__ldg(xr + j), __ldg(wr + j), cur);
        float m = 0.f;
#pragma unroll
        for (int t = 0; t < 15; t++) {
            float r = (m > THRV) ? THRV : 0.f;
            m = 0.90f * m + cur - r;
            g_spk1[t * (NB * 256) + i] = __float2half_rn(m > THRV ? 1.f : 0.f);
        }
    }
}

// ---------------- W stage producer ------------------------------------------
// Stage p (global index), data = source stage s_src of (Hg,Lg). All threads.
// 1024 tasks x cp16 PAIR = 16384 halfs = 2 chunks x (hi,lo) x 128 rows x 32.
// mb layout: full[j] = mb + j*16, empty[j] = mb + j*16 + 8, amb = mb + 48.
__device__ __forceinline__ void produce_w(unsigned int mb, __half* ring,
                                          const __half* Hg, const __half* Lg,
                                          int s_src, unsigned int p, int tid) {
    unsigned int slot = p % NRING;
    if (p >= NRING) mbar_wait(mb + slot * 16 + 8, ((p / NRING) - 1) & 1);
    __half* dbuf = ring + slot * SWB_H;
#pragma unroll
    for (int i = 0; i < 2; i++) {
        int id = i * 512 + tid;
        int kc2 = id >> 9;
        int hl = (id >> 8) & 1;
        int rr = (id >> 1) & 127;
        int sg = (id & 1) * 16;
        const __half* src =
            (hl ? Lg : Hg) + (size_t)rr * 256 + s_src * 64 + kc2 * 32 + sg;
        __half* dst = dbuf + (kc2 * 2 + hl) * T_H + rr * 40 + sg;
        cp16(dst, src);
        cp16(dst + 8, src + 8);
    }
    cpasync_arrive(mb + slot * 16);
}

// ---------------- GEMM: A resident, W via mbarrier ring ---------------------
// 16 warps (4m x 4n), warp tile 32x32, acc[2][4][4]. Consumes 4 global stages
// starting at ci; produces ci+1..ci+4 (next tile's stage 0 via nH/nL at s==3).
__device__ __forceinline__ void gemm16(
    const __half* sA, __half* ring, unsigned int mb,
    const __half* __restrict__ Hg, const __half* __restrict__ Lg,
    const __half* nH, const __half* nL, unsigned int& ci,
    int tid, int lane, int wm, int wn, float acc[2][4][4]) {
    const int aRowL = (lane & 15);
    const int aColL = (lane >> 4) * 8;
    const int bRowL = (lane & 7) + ((lane >> 4) & 1) * 8;
    const int bColL = ((lane >> 3) & 1) * 8;

#pragma unroll 1
    for (int s = 0; s < 4; s++) {
        unsigned int c = ci;
        // produce stage c+1
        if (s < 3) produce_w(mb, ring, Hg, Lg, s + 1, c + 1, tid);
        else if (nH) produce_w(mb, ring, nH, nL, 0, c + 1, tid);

        // consume stage c
        unsigned int slot = c % NRING;
        mbar_wait(mb + slot * 16, (c / NRING) & 1);
        const __half* wbuf = ring + slot * SWB_H;

#pragma unroll
        for (int kc2 = 0; kc2 < 2; kc2++) {
            const __half* cA = sA + (s * 2 + kc2) * T_H;
            const __half* sH = wbuf + kc2 * 2 * T_H;
            const __half* sL = sH + T_H;
#pragma unroll
            for (int kk = 0; kk < 2; kk++) {
                unsigned int aF[2][4];
#pragma unroll
                for (int mt = 0; mt < 2; mt++) {
                    unsigned int ad =
                        s2u(cA + (wm * 32 + mt * 16 + aRowL) * 40 + kk * 16 + aColL);
                    ldmx4(aF[mt][0], aF[mt][1], aF[mt][2], aF[mt][3], ad);
                }
                unsigned int hF[4][2], lF[4][2];
#pragma unroll
                for (int p = 0; p < 2; p++) {
                    unsigned int r0, r1, r2, r3;
                    unsigned int bd =
                        s2u(sH + (wn * 32 + p * 16 + bRowL) * 40 + kk * 16 + bColL);
                    ldmx4(r0, r1, r2, r3, bd);
                    hF[2 * p][0] = r0; hF[2 * p][1] = r1;
                    hF[2 * p + 1][0] = r2; hF[2 * p + 1][1] = r3;
                    unsigned int ld =
                        s2u(sL + (wn * 32 + p * 16 + bRowL) * 40 + kk * 16 + bColL);
                    ldmx4(r0, r1, r2, r3, ld);
                    lF[2 * p][0] = r0; lF[2 * p][1] = r1;
                    lF[2 * p + 1][0] = r2; lF[2 * p + 1][1] = r3;
                }
#pragma unroll
                for (int mt = 0; mt < 2; mt++)
#pragma unroll
                    for (int nt = 0; nt < 4; nt++) {
                        mma16816(acc[mt][nt], aF[mt], hF[nt]);
                        mma16816(acc[mt][nt], aF[mt], lF[nt]);
                    }
            }
        }
        __syncwarp();
        if (lane == 0) mbar_arrive(mb + slot * 16 + 8);   // empty[slot]
        ci = c + 1;
    }
}

// ---------------- the persistent SNN kernel --------------------------------
__global__ __launch_bounds__(512, 1) void k_snn(
    const __half* __restrict__ spk1, const __half* __restrict__ Wh,
    const __half* __restrict__ Wl,
    const float* __restrict__ b2, const float* __restrict__ b3,
    const float* __restrict__ b4, const float* __restrict__ b5,
    float* __restrict__ mem2, float* __restrict__ mem3,
    float* __restrict__ mem4, float* __restrict__ mem5,
    const float* __restrict__ W6, const float* __restrict__ b6,
    float* __restrict__ out) {
    extern __shared__ __half smbuf[];
    __half* sA = smbuf;
    __half* ring = smbuf + SA_H;
    const unsigned int mb = s2u(smbuf + SA_H + SW_H);   // 7 mbarriers (56 B)
    float* ws = (float*)(smbuf + SA_H + SW_H + 32);     // 64 B past mbars

    const int tid = threadIdx.x;
    const int lane = tid & 31, wid = tid >> 5;
    const int wm = wid >> 2, wn = wid & 3;     // 4m x 4n warps
    const int m0 = blockIdx.x * 128;

    // init mbarriers: full[0..2] count 512, empty[0..2] count 16, amb count 512
    if (tid == 0) {
#pragma unroll
        for (int j = 0; j < NRING; j++) {
            asm volatile("mbarrier.init.shared.b64 [%0], 512;" :: "r"(mb + j * 16) : "memory");
            asm volatile("mbarrier.init.shared.b64 [%0], 16;" :: "r"(mb + j * 16 + 8) : "memory");
        }
        asm volatile("mbarrier.init.shared.b64 [%0], 512;" :: "r"(mb + 48) : "memory");
    }
    for (int i = tid; i < 384; i += 512) ws[i] = W6[i];
    __syncthreads();

    const int rowL = wm * 32 + (lane >> 2);
    const int colL = wn * 32 + (lane & 3) * 2;

    float o0 = 0.f, o1 = 0.f, o2 = 0.f;
    const float b60 = __ldg(b6 + 0), b61 = __ldg(b6 + 1), b62 = __ldg(b6 + 2);

    const __half* WhL[4] = {Wh, Wh + 65536, Wh + 131072, Wh + 196608};
    const __half* WlL[4] = {Wl, Wl + 65536, Wl + 131072, Wl + 196608};
    const float* biasL[3] = {b2, b3, b4};
    float* memL[3] = {mem2, mem3, mem4};
    const float betaL[3] = {0.88f, 0.86f, 0.84f};

    unsigned int ci = 0;
    // prime: produce global stage 0 (= step 0, layer 2 ht0, stage 0)
    produce_w(mb, ring, WhL[0], WlL[0], 0, 0, tid);

#pragma unroll 1
    for (int t = 0; t < 15; ++t) {
        // ---- stage layer-1 spikes into sA (2048 tasks, cp16 PAIR each) ----
        {
            const __half* Ag = spk1 + ((size_t)t * NB + m0) * 256;
#pragma unroll
            for (int i = 0; i < 4; i++) {
                int id = i * 512 + tid;
                int c = id >> 8;
                int rr = (id >> 1) & 127;
                int sg = (id & 1) * 16;
                __half* dst = sA + c * T_H + rr * 40 + sg;
                const __half* src = Ag + rr * 256 + c * 32 + sg;
                cp16(dst, src);
                cp16(dst + 8, src + 8);
            }
            cpasync_arrive(mb + 48);
        }
        mbar_wait(mb + 48, t & 1);   // per-thread; no rendezvous

        // ---- layers 2..4 (N=256: two 128-col tiles) -----------------------
#pragma unroll 1
        for (int l = 0; l < 3; l++) {
            const float beta = betaL[l];
            float* mem = memL[l];
            const float* bias = biasL[l];
            __half2 s0v[2][4][2];

#pragma unroll 1
            for (int ht = 0; ht < 2; ht++) {
                const __half *nH, *nL;
                if (ht == 0) { nH = WhL[l] + 128 * 256; nL = WlL[l] + 128 * 256; }
                else if (l < 2) { nH = WhL[l + 1]; nL = WlL[l + 1]; }
                else { nH = WhL[3]; nL = WlL[3]; }

                float acc[2][4][4];
#pragma unroll
                for (int i = 0; i < 2; i++)
#pragma unroll
                    for (int j = 0; j < 4; j++)
#pragma unroll
                        for (int q = 0; q < 4; q++) acc[i][j][q] = 0.f;

                gemm16(sA, ring, mb, WhL[l] + ht * 128 * 256,
                       WlL[l] + ht * 128 * 256, nH, nL, ci,
                       tid, lane, wm, wn, acc);

                if (ht == 1) __syncthreads();   // all warps done reading sA

#pragma unroll
                for (int mt = 0; mt < 2; mt++) {
                    int rl = rowL + mt * 16;
                    int r = m0 + rl;
#pragma unroll
                    for (int nt = 0; nt < 4; nt++) {
                        int c = ht * 128 + colL + nt * 8;
                        size_t gi0 = (size_t)r * 256 + c;
                        size_t gi1 = gi0 + (size_t)8 * 256;
                        float2 bb = *(const float2*)(bias + c);
                        float2 mp0 = *(float2*)(mem + gi0);
                        float2 mp1 = *(float2*)(mem + gi1);
                        float cv0 = acc[mt][nt][0] + bb.x;
                        float cv1 = acc[mt][nt][1] + bb.y;
                        float cv2 = acc[mt][nt][2] + bb.x;
                        float cv3 = acc[mt][nt][3] + bb.y;
                        float n0v = beta * mp0.x + cv0 - (mp0.x > THRV ? THRV : 0.f);
                        float n1v = beta * mp0.y + cv1 - (mp0.y > THRV ? THRV : 0.f);
                        float n2v = beta * mp1.x + cv2 - (mp1.x > THRV ? THRV : 0.f);
                        float n3v = beta * mp1.y + cv3 - (mp1.y > THRV ? THRV : 0.f);
                        *(float2*)(mem + gi0) = make_float2(n0v, n1v);
                        *(float2*)(mem + gi1) = make_float2(n2v, n3v);
                        __half2 p0 = __floats2half2_rn(n0v > THRV ? 1.f : 0.f,
                                                       n1v > THRV ? 1.f : 0.f);
                        __half2 p1 = __floats2half2_rn(n2v > THRV ? 1.f : 0.f,
                                                       n3v > THRV ? 1.f : 0.f);
                        if (ht == 0) {
                            s0v[mt][nt][0] = p0;
                            s0v[mt][nt][1] = p1;
                        } else {
                            int cc = c & 31;
                            __half* base = sA + (c >> 5) * T_H;
                            *(__half2*)(base + rl * 40 + cc) = p0;
                            *(__half2*)(base + (rl + 8) * 40 + cc) = p1;
                        }
                    }
                }
            }
            // park tile-0 spikes into sA
#pragma unroll
            for (int mt = 0; mt < 2; mt++) {
                int rl = rowL + mt * 16;
#pragma unroll
                for (int nt = 0; nt < 4; nt++) {
                    int c = colL + nt * 8;
                    int cc = c & 31;
                    __half* base = sA + (c >> 5) * T_H;
                    *(__half2*)(base + rl * 40 + cc) = s0v[mt][nt][0];
                    *(__half2*)(base + (rl + 8) * 40 + cc) = s0v[mt][nt][1];
                }
            }
            __syncthreads();
        }

        // ---- layer 5 (N=128) + fused output head --------------------------
        {
            const __half* nH = (t < 14) ? WhL[0] : nullptr;
            const __half* nL = (t < 14) ? WlL[0] : nullptr;

            float acc[2][4][4];
#pragma unroll
            for (int i = 0; i < 2; i++)
#pragma unroll
                for (int j = 0; j < 4; j++)
#pragma unroll
                    for (int q = 0; q < 4; q++) acc[i][j][q] = 0.f;

            gemm16(sA, ring, mb, WhL[3], WlL[3], nH, nL, ci,
                   tid, lane, wm, wn, acc);

            __syncthreads();   // all warps done reading sA

#pragma unroll
            for (int mt = 0; mt < 2; mt++) {
                int rl = rowL + mt * 16;
                int r = m0 + rl;
#pragma unroll
                for (int nt = 0; nt < 4; nt++) {
                    int c = colL + nt * 8;
                    size_t gi0 = (size_t)r * 128 + c;
                    size_t gi1 = gi0 + (size_t)8 * 128;
                    float2 bb = *(const float2*)(b5 + c);
                    float2 mp0 = *(float2*)(mem5 + gi0);
                    float2 mp1 = *(float2*)(mem5 + gi1);
                    float cv0 = acc[mt][nt][0] + bb.x;
                    float cv1 = acc[mt][nt][1] + bb.y;
                    float cv2 = acc[mt][nt][2] + bb.x;
                    float cv3 = acc[mt][nt][3] + bb.y;
                    float n0v = 0.82f * mp0.x + cv0 - (mp0.x > THRV ? THRV : 0.f);
                    float n1v = 0.82f * mp0.y + cv1 - (mp0.y > THRV ? THRV : 0.f);
                    float n2v = 0.82f * mp1.x + cv2 - (mp1.x > THRV ? THRV : 0.f);
                    float n3v = 0.82f * mp1.y + cv3 - (mp1.y > THRV ? THRV : 0.f);
                    *(float2*)(mem5 + gi0) = make_float2(n0v, n1v);
                    *(float2*)(mem5 + gi1) = make_float2(n2v, n3v);
                    int cc = c & 31;
                    __half* base = sA + (c >> 5) * T_H;
                    *(__half2*)(base + rl * 40 + cc) =
                        __floats2half2_rn(n0v > THRV ? 1.f : 0.f,
                                          n1v > THRV ? 1.f : 0.f);
                    *(__half2*)(base + (rl + 8) * 40 + cc) =
                        __floats2half2_rn(n2v > THRV ? 1.f : 0.f,
                                          n3v > THRV ? 1.f : 0.f);
                }
            }
            __syncthreads();

            if (tid < 128) {
                float s0 = b60, s1 = b61, s2v = b62;
#pragma unroll
                for (int ch = 0; ch < 4; ch++) {
                    const __half* sr = sA + ch * T_H + tid * 40;
#pragma unroll
                    for (int k = 0; k < 32; k++) {
                        float v = __half2float(sr[k]);
                        int x = ch * 32 + k;
                        s0 = fmaf(v, ws[x], s0);
                        s1 = fmaf(v, ws[128 + x], s1);
                        s2v = fmaf(v, ws[256 + x], s2v);
                    }
                }
                o0 += s0; o1 += s1; o2 += s2v;
            }
            __syncthreads();   // head done before next step's A restage
        }
    }

    if (tid < 128) {
        int b = m0 + tid;
        const float inv = 1.f / 15.f;
        out[b * 3 + 0] = o0 * inv;
        out[b * 3 + 1] = o1 * inv;
        out[b * 3 + 2] = o2 * inv;
    }
}

// ---------------- launch --------------------------------------------------
extern "C" void kernel_launch(void* const* d_in, const int* in_sizes, int n_in,
                              void* d_out, int out_size) {
    const float* x  = (const float*)d_in[0];
    const float* W1 = (const float*)d_in[1];
    const float* b1 = (const float*)d_in[2];
    const float* W2 = (const float*)d_in[3];
    const float* b2 = (const float*)d_in[4];
    const float* W3 = (const float*)d_in[5];
    const float* b3 = (const float*)d_in[6];
    const float* W4 = (const float*)d_in[7];
    const float* b4 = (const float*)d_in[8];
    const float* W5 = (const float*)d_in[9];
    const float* b5 = (const float*)d_in[10];
    const float* W6 = (const float*)d_in[11];
    const float* b6 = (const float*)d_in[12];
    float* out = (float*)d_out;

    __half *p_spk1, *p_Wh, *p_Wl;
    float *p_mem2, *p_mem3, *p_mem4, *p_mem5;
    cudaGetSymbolAddress((void**)&p_spk1, g_spk1);
    cudaGetSymbolAddress((void**)&p_Wh, g_Wh);
    cudaGetSymbolAddress((void**)&p_Wl, g_Wl);
    cudaGetSymbolAddress((void**)&p_mem2, g_mem2);
    cudaGetSymbolAddress((void**)&p_mem3, g_mem3);
    cudaGetSymbolAddress((void**)&p_mem4, g_mem4);
    cudaGetSymbolAddress((void**)&p_mem5, g_mem5);

    cudaFuncSetAttribute(k_snn, cudaFuncAttributeMaxDynamicSharedMemorySize, SMEMT);

    k_setup<<<2048, 256>>>(x, W1, b1, W2, W3, W4, W5);
    k_snn<<<NB / 128, 512, SMEMT>>>(p_spk1, p_Wh, p_Wl, b2, b3, b4, b5,
                                    p_mem2, p_mem3, p_mem4, p_mem5,
                                    W6, b6, out);
}

// round 15
// speedup vs baseline: 1.2674x; 1.0127x over previous
#include <cuda_runtime.h>
#include <cuda_fp16.h>
#include <cstdint>

// MultiLayerDeepSNN: 15-step LIF SNN, B=16384, layers 6->256->256->256->256->128->3.
// Round 15: R14 (mbarrier-ring, warp drift) + zero-reg-cost scheduling:
//  (1) kk0 A-ldsm hoisted above the full-wait (A independent of W ring),
//  (2) empty[slot] arrive moved to right after the stage's last W-ldsm
//      (before kk1 MMAs) so the producer unblocks earlier.

#define NB 16384
#define THRV 1.0f

#define T_H   (128 * 40)          // halfs per 32-col chunk (5120)
#define SA_H  (8 * T_H)           // A: 8 chunks = 128x256 halfs (81920 B)
#define SWB_H (4 * T_H)           // one BK=64 W stage: 2 chunks x (hi,lo) (40960 B)
#define NRING 3
#define SW_H  (NRING * SWB_H)     // ring (122880 B)
#define SMEMT ((SA_H + SW_H) * 2 + 64 + 1536)   // + mbars + W6 = 206016 B

// ---------------- scratch -------------------------------------------------
__device__ __half g_spk1[15 * NB * 256];
__device__ float g_mem2[NB * 256];
__device__ float g_mem3[NB * 256];
__device__ float g_mem4[NB * 256];
__device__ float g_mem5[NB * 128];
__device__ __half g_Wh[3 * 65536 + 32768];
__device__ __half g_Wl[3 * 65536 + 32768];

// ---------------- helpers -------------------------------------------------
__device__ __forceinline__ unsigned int s2u(const void* p) {
    return (unsigned int)__cvta_generic_to_shared(p);
}
__device__ __forceinline__ void cp16(void* dst, const void* src) {
    asm volatile("cp.async.cg.shared.global [%0], [%1], 16;"
                 :: "r"(s2u(dst)), "l"(src));
}
__device__ __forceinline__ void ldmx4(unsigned int& r0, unsigned int& r1,
                                      unsigned int& r2, unsigned int& r3,
                                      unsigned int addr) {
    asm volatile("ldmatrix.sync.aligned.m8n8.x4.shared.b16 {%0,%1,%2,%3}, [%4];"
                 : "=r"(r0), "=r"(r1), "=r"(r2), "=r"(r3) : "r"(addr));
}
__device__ __forceinline__ void mma16816(float* c, const unsigned int* a,
                                         const unsigned int* b) {
    asm volatile(
        "mma.sync.aligned.m16n8k16.row.col.f32.f16.f16.f32 "
        "{%0,%1,%2,%3},{%4,%5,%6,%7},{%8,%9},{%0,%1,%2,%3};"
        : "+f"(c[0]), "+f"(c[1]), "+f"(c[2]), "+f"(c[3])
        : "r"(a[0]), "r"(a[1]), "r"(a[2]), "r"(a[3]), "r"(b[0]), "r"(b[1]));
}
__device__ __forceinline__ void mbar_wait(unsigned int addr, unsigned int phase) {
    asm volatile(
        "{\n\t.reg .pred P;\n\tLW_%=:\n\t"
        "mbarrier.try_wait.parity.acquire.cta.shared::cta.b64 P, [%0], %1, 0x989680;\n\t"
        "@P bra LD_%=;\n\tbra LW_%=;\n\tLD_%=:\n\t}"
        :: "r"(addr), "r"(phase) : "memory");
}
__device__ __forceinline__ void mbar_arrive(unsigned int addr) {
    asm volatile("mbarrier.arrive.shared.b64 _, [%0];" :: "r"(addr) : "memory");
}
__device__ __forceinline__ void cpasync_arrive(unsigned int addr) {
    asm volatile("cp.async.mbarrier.arrive.noinc.shared.b64 [%0];"
                 :: "r"(addr) : "memory");
}

// ---------------- merged setup: zero mems + split weights + layer1 chain ---
__global__ void k_setup(const float* __restrict__ x, const float* __restrict__ W1,
                        const float* __restrict__ b1,
                        const float* __restrict__ W2, const float* __restrict__ W3,
                        const float* __restrict__ W4, const float* __restrict__ W5) {
    int idx = blockIdx.x * blockDim.x + threadIdx.x;
    int stride = gridDim.x * blockDim.x;
    for (int i = idx; i < NB * 256; i += stride) {
        g_mem2[i] = 0.f; g_mem3[i] = 0.f; g_mem4[i] = 0.f;
    }
    for (int i = idx; i < NB * 128; i += stride) g_mem5[i] = 0.f;

    for (int i = idx; i < 65536; i += stride) {
        float w = W2[i]; __half h = __float2half_rn(w);
        g_Wh[i] = h; g_Wl[i] = __float2half_rn(w - __half2float(h));
        w = W3[i]; h = __float2half_rn(w);
        g_Wh[65536 + i] = h; g_Wl[65536 + i] = __float2half_rn(w - __half2float(h));
        w = W4[i]; h = __float2half_rn(w);
        g_Wh[131072 + i] = h; g_Wl[131072 + i] = __float2half_rn(w - __half2float(h));
    }
    for (int i = idx; i < 32768; i += stride) {
        float w = W5[i]; __half h = __float2half_rn(w);
        g_Wh[196608 + i] = h; g_Wl[196608 + i] = __float2half_rn(w - __half2float(h));
    }

    for (int i = idx; i < NB * 256; i += stride) {
        int b = i >> 8, o = i & 255;
        const float* xr = x + b * 6;
        const float* wr = W1 + o * 6;
        float cur = __ldg(b1 + o);
#pragma unroll
        for (int j = 0; j < 6; j++) cur = fmaf(__ldg(xr + j), __ldg(wr + j), cur);
        float m = 0.f;
#pragma unroll
        for (int t = 0; t < 15; t++) {
            float r = (m > THRV) ? THRV : 0.f;
            m = 0.90f * m + cur - r;
            g_spk1[t * (NB * 256) + i] = __float2half_rn(m > THRV ? 1.f : 0.f);
        }
    }
}

// ---------------- W stage producer ------------------------------------------
// 1024 tasks x cp16 PAIR = 16384 halfs = 2 chunks x (hi,lo) x 128 rows x 32.
// mb layout: full[j] = mb + j*16, empty[j] = mb + j*16 + 8, amb = mb + 48.
__device__ __forceinline__ void produce_w(unsigned int mb, __half* ring,
                                          const __half* Hg, const __half* Lg,
                                          int s_src, unsigned int p, int tid) {
    unsigned int slot = p % NRING;
    if (p >= NRING) mbar_wait(mb + slot * 16 + 8, ((p / NRING) - 1) & 1);
    __half* dbuf = ring + slot * SWB_H;
#pragma unroll
    for (int i = 0; i < 2; i++) {
        int id = i * 512 + tid;
        int kc2 = id >> 9;
        int hl = (id >> 8) & 1;
        int rr = (id >> 1) & 127;
        int sg = (id & 1) * 16;
        const __half* src =
            (hl ? Lg : Hg) + (size_t)rr * 256 + s_src * 64 + kc2 * 32 + sg;
        __half* dst = dbuf + (kc2 * 2 + hl) * T_H + rr * 40 + sg;
        cp16(dst, src);
        cp16(dst + 8, src + 8);
    }
    cpasync_arrive(mb + slot * 16);
}

// ---------------- GEMM: A resident, W via mbarrier ring ---------------------
// 16 warps (4m x 4n), warp tile 32x32, acc[2][4][4].
__device__ __forceinline__ void gemm16(
    const __half* sA, __half* ring, unsigned int mb,
    const __half* __restrict__ Hg, const __half* __restrict__ Lg,
    const __half* nH, const __half* nL, unsigned int& ci,
    int tid, int lane, int wm, int wn, float acc[2][4][4]) {
    const int aRowL = (lane & 15);
    const int aColL = (lane >> 4) * 8;
    const int bRowL = (lane & 7) + ((lane >> 4) & 1) * 8;
    const int bColL = ((lane >> 3) & 1) * 8;

#pragma unroll 1
    for (int s = 0; s < 4; s++) {
        unsigned int c = ci;
        // produce stage c+1 (cp.async issue; may wait empty[(c+1)%3])
        if (s < 3) produce_w(mb, ring, Hg, Lg, s + 1, c + 1, tid);
        else if (nH) produce_w(mb, ring, nH, nL, 0, c + 1, tid);

        const __half* cA = sA + (s * 2) * T_H;       // kk pair base for stage s
        // (1) kk0 A-ldsm hoisted ABOVE the full wait (A independent of W ring)
        unsigned int aF[2][4];
#pragma unroll
        for (int mt = 0; mt < 2; mt++) {
            unsigned int ad =
                s2u(cA + (wm * 32 + mt * 16 + aRowL) * 40 + 0 * 16 + aColL);
            ldmx4(aF[mt][0], aF[mt][1], aF[mt][2], aF[mt][3], ad);
        }

        // consume stage c
        unsigned int slot = c % NRING;
        mbar_wait(mb + slot * 16, (c / NRING) & 1);
        const __half* wbuf = ring + slot * SWB_H;

#pragma unroll
        for (int kc2 = 0; kc2 < 2; kc2++) {
            const __half* cAk = sA + (s * 2 + kc2) * T_H;
            const __half* sH = wbuf + kc2 * 2 * T_H;
            const __half* sL = sH + T_H;
#pragma unroll
            for (int kk = 0; kk < 2; kk++) {
                if (!(kc2 == 0 && kk == 0)) {   // kk0 of kc2=0 preloaded above
#pragma unroll
                    for (int mt = 0; mt < 2; mt++) {
                        unsigned int ad =
                            s2u(cAk + (wm * 32 + mt * 16 + aRowL) * 40 + kk * 16 + aColL);
                        ldmx4(aF[mt][0], aF[mt][1], aF[mt][2], aF[mt][3], ad);
                    }
                }
                unsigned int hF[4][2], lF[4][2];
#pragma unroll
                for (int p = 0; p < 2; p++) {
                    unsigned int r0, r1, r2, r3;
                    unsigned int bd =
                        s2u(sH + (wn * 32 + p * 16 + bRowL) * 40 + kk * 16 + bColL);
                    ldmx4(r0, r1, r2, r3, bd);
                    hF[2 * p][0] = r0; hF[2 * p][1] = r1;
                    hF[2 * p + 1][0] = r2; hF[2 * p + 1][1] = r3;
                    unsigned int ld =
                        s2u(sL + (wn * 32 + p * 16 + bRowL) * 40 + kk * 16 + bColL);
                    ldmx4(r0, r1, r2, r3, ld);
                    lF[2 * p][0] = r0; lF[2 * p][1] = r1;
                    lF[2 * p + 1][0] = r2; lF[2 * p + 1][1] = r3;
                }
                // (2) after the stage's LAST W-ldsm, slot is no longer needed:
                // signal empty before issuing the final MMA block.
                if (kc2 == 1 && kk == 1 && lane == 0)
                    mbar_arrive(mb + slot * 16 + 8);
#pragma unroll
                for (int mt = 0; mt < 2; mt++)
#pragma unroll
                    for (int nt = 0; nt < 4; nt++) {
                        mma16816(acc[mt][nt], aF[mt], hF[nt]);
                        mma16816(acc[mt][nt], aF[mt], lF[nt]);
                    }
            }
        }
        ci = c + 1;
    }
}

// ---------------- the persistent SNN kernel --------------------------------
__global__ __launch_bounds__(512, 1) void k_snn(
    const __half* __restrict__ spk1, const __half* __restrict__ Wh,
    const __half* __restrict__ Wl,
    const float* __restrict__ b2, const float* __restrict__ b3,
    const float* __restrict__ b4, const float* __restrict__ b5,
    float* __restrict__ mem2, float* __restrict__ mem3,
    float* __restrict__ mem4, float* __restrict__ mem5,
    const float* __restrict__ W6, const float* __restrict__ b6,
    float* __restrict__ out) {
    extern __shared__ __half smbuf[];
    __half* sA = smbuf;
    __half* ring = smbuf + SA_H;
    const unsigned int mb = s2u(smbuf + SA_H + SW_H);   // 7 mbarriers (56 B)
    float* ws = (float*)(smbuf + SA_H + SW_H + 32);     // 64 B past mbars

    const int tid = threadIdx.x;
    const int lane = tid & 31, wid = tid >> 5;
    const int wm = wid >> 2, wn = wid & 3;     // 4m x 4n warps
    const int m0 = blockIdx.x * 128;

    if (tid == 0) {
#pragma unroll
        for (int j = 0; j < NRING; j++) {
            asm volatile("mbarrier.init.shared.b64 [%0], 512;" :: "r"(mb + j * 16) : "memory");
            asm volatile("mbarrier.init.shared.b64 [%0], 16;" :: "r"(mb + j * 16 + 8) : "memory");
        }
        asm volatile("mbarrier.init.shared.b64 [%0], 512;" :: "r"(mb + 48) : "memory");
    }
    for (int i = tid; i < 384; i += 512) ws[i] = W6[i];
    __syncthreads();

    const int rowL = wm * 32 + (lane >> 2);
    const int colL = wn * 32 + (lane & 3) * 2;

    float o0 = 0.f, o1 = 0.f, o2 = 0.f;
    const float b60 = __ldg(b6 + 0), b61 = __ldg(b6 + 1), b62 = __ldg(b6 + 2);

    const __half* WhL[4] = {Wh, Wh + 65536, Wh + 131072, Wh + 196608};
    const __half* WlL[4] = {Wl, Wl + 65536, Wl + 131072, Wl + 196608};
    const float* biasL[3] = {b2, b3, b4};
    float* memL[3] = {mem2, mem3, mem4};
    const float betaL[3] = {0.88f, 0.86f, 0.84f};

    unsigned int ci = 0;
    produce_w(mb, ring, WhL[0], WlL[0], 0, 0, tid);   // prime stage 0

#pragma unroll 1
    for (int t = 0; t < 15; ++t) {
        // ---- stage layer-1 spikes into sA (2048 tasks, cp16 PAIR each) ----
        {
            const __half* Ag = spk1 + ((size_t)t * NB + m0) * 256;
#pragma unroll
            for (int i = 0; i < 4; i++) {
                int id = i * 512 + tid;
                int c = id >> 8;
                int rr = (id >> 1) & 127;
                int sg = (id & 1) * 16;
                __half* dst = sA + c * T_H + rr * 40 + sg;
                const __half* src = Ag + rr * 256 + c * 32 + sg;
                cp16(dst, src);
                cp16(dst + 8, src + 8);
            }
            cpasync_arrive(mb + 48);
        }
        mbar_wait(mb + 48, t & 1);   // per-thread; no rendezvous

        // ---- layers 2..4 (N=256: two 128-col tiles) -----------------------
#pragma unroll 1
        for (int l = 0; l < 3; l++) {
            const float beta = betaL[l];
            float* mem = memL[l];
            const float* bias = biasL[l];
            __half2 s0v[2][4][2];

#pragma unroll 1
            for (int ht = 0; ht < 2; ht++) {
                const __half *nH, *nL;
                if (ht == 0) { nH = WhL[l] + 128 * 256; nL = WlL[l] + 128 * 256; }
                else if (l < 2) { nH = WhL[l + 1]; nL = WlL[l + 1]; }
                else { nH = WhL[3]; nL = WlL[3]; }

                float acc[2][4][4];
#pragma unroll
                for (int i = 0; i < 2; i++)
#pragma unroll
                    for (int j = 0; j < 4; j++)
#pragma unroll
                        for (int q = 0; q < 4; q++) acc[i][j][q] = 0.f;

                gemm16(sA, ring, mb, WhL[l] + ht * 128 * 256,
                       WlL[l] + ht * 128 * 256, nH, nL, ci,
                       tid, lane, wm, wn, acc);

                if (ht == 1) __syncthreads();   // all warps done reading sA

#pragma unroll
                for (int mt = 0; mt < 2; mt++) {
                    int rl = rowL + mt * 16;
                    int r = m0 + rl;
#pragma unroll
                    for (int nt = 0; nt < 4; nt++) {
                        int c = ht * 128 + colL + nt * 8;
                        size_t gi0 = (size_t)r * 256 + c;
                        size_t gi1 = gi0 + (size_t)8 * 256;
                        float2 bb = *(const float2*)(bias + c);
                        float2 mp0 = *(float2*)(mem + gi0);
                        float2 mp1 = *(float2*)(mem + gi1);
                        float cv0 = acc[mt][nt][0] + bb.x;
                        float cv1 = acc[mt][nt][1] + bb.y;
                        float cv2 = acc[mt][nt][2] + bb.x;
                        float cv3 = acc[mt][nt][3] + bb.y;
                        float n0v = beta * mp0.x + cv0 - (mp0.x > THRV ? THRV : 0.f);
                        float n1v = beta * mp0.y + cv1 - (mp0.y > THRV ? THRV : 0.f);
                        float n2v = beta * mp1.x + cv2 - (mp1.x > THRV ? THRV : 0.f);
                        float n3v = beta * mp1.y + cv3 - (mp1.y > THRV ? THRV : 0.f);
                        *(float2*)(mem + gi0) = make_float2(n0v, n1v);
                        *(float2*)(mem + gi1) = make_float2(n2v, n3v);
                        __half2 p0 = __floats2half2_rn(n0v > THRV ? 1.f : 0.f,
                                                       n1v > THRV ? 1.f : 0.f);
                        __half2 p1 = __floats2half2_rn(n2v > THRV ? 1.f : 0.f,
                                                       n3v > THRV ? 1.f : 0.f);
                        if (ht == 0) {
                            s0v[mt][nt][0] = p0;
                            s0v[mt][nt][1] = p1;
                        } else {
                            int cc = c & 31;
                            __half* base = sA + (c >> 5) * T_H;
                            *(__half2*)(base + rl * 40 + cc) = p0;
                            *(__half2*)(base + (rl + 8) * 40 + cc) = p1;
                        }
                    }
                }
            }
            // park tile-0 spikes into sA
#pragma unroll
            for (int mt = 0; mt < 2; mt++) {
                int rl = rowL + mt * 16;
#pragma unroll
                for (int nt = 0; nt < 4; nt++) {
                    int c = colL + nt * 8;
                    int cc = c & 31;
                    __half* base = sA + (c >> 5) * T_H;
                    *(__half2*)(base + rl * 40 + cc) = s0v[mt][nt][0];
                    *(__half2*)(base + (rl + 8) * 40 + cc) = s0v[mt][nt][1];
                }
            }
            __syncthreads();
        }

        // ---- layer 5 (N=128) + fused output head --------------------------
        {
            const __half* nH = (t < 14) ? WhL[0] : nullptr;
            const __half* nL = (t < 14) ? WlL[0] : nullptr;

            float acc[2][4][4];
#pragma unroll
            for (int i = 0; i < 2; i++)
#pragma unroll
                for (int j = 0; j < 4; j++)
#pragma unroll
                    for (int q = 0; q < 4; q++) acc[i][j][q] = 0.f;

            gemm16(sA, ring, mb, WhL[3], WlL[3], nH, nL, ci,
                   tid, lane, wm, wn, acc);

            __syncthreads();   // all warps done reading sA

#pragma unroll
            for (int mt = 0; mt < 2; mt++) {
                int rl = rowL + mt * 16;
                int r = m0 + rl;
#pragma unroll
                for (int nt = 0; nt < 4; nt++) {
                    int c = colL + nt * 8;
                    size_t gi0 = (size_t)r * 128 + c;
                    size_t gi1 = gi0 + (size_t)8 * 128;
                    float2 bb = *(const float2*)(b5 + c);
                    float2 mp0 = *(float2*)(mem5 + gi0);
                    float2 mp1 = *(float2*)(mem5 + gi1);
                    float cv0 = acc[mt][nt][0] + bb.x;
                    float cv1 = acc[mt][nt][1] + bb.y;
                    float cv2 = acc[mt][nt][2] + bb.x;
                    float cv3 = acc[mt][nt][3] + bb.y;
                    float n0v = 0.82f * mp0.x + cv0 - (mp0.x > THRV ? THRV : 0.f);
                    float n1v = 0.82f * mp0.y + cv1 - (mp0.y > THRV ? THRV : 0.f);
                    float n2v = 0.82f * mp1.x + cv2 - (mp1.x > THRV ? THRV : 0.f);
                    float n3v = 0.82f * mp1.y + cv3 - (mp1.y > THRV ? THRV : 0.f);
                    *(float2*)(mem5 + gi0) = make_float2(n0v, n1v);
                    *(float2*)(mem5 + gi1) = make_float2(n2v, n3v);
                    int cc = c & 31;
                    __half* base = sA + (c >> 5) * T_H;
                    *(__half2*)(base + rl * 40 + cc) =
                        __floats2half2_rn(n0v > THRV ? 1.f : 0.f,
                                          n1v > THRV ? 1.f : 0.f);
                    *(__half2*)(base + (rl + 8) * 40 + cc) =
                        __floats2half2_rn(n2v > THRV ? 1.f : 0.f,
                                          n3v > THRV ? 1.f : 0.f);
                }
            }
            __syncthreads();

            if (tid < 128) {
                float s0 = b60, s1 = b61, s2v = b62;
#pragma unroll
                for (int ch = 0; ch < 4; ch++) {
                    const __half* sr = sA + ch * T_H + tid * 40;
#pragma unroll
                    for (int k = 0; k < 32; k++) {
                        float v = __half2float(sr[k]);
                        int x = ch * 32 + k;
                        s0 = fmaf(v, ws[x], s0);
                        s1 = fmaf(v, ws[128 + x], s1);
                        s2v = fmaf(v, ws[256 + x], s2v);
                    }
                }
                o0 += s0; o1 += s1; o2 += s2v;
            }
            __syncthreads();   // head done before next step's A restage
        }
    }

    if (tid < 128) {
        int b = m0 + tid;
        const float inv = 1.f / 15.f;
        out[b * 3 + 0] = o0 * inv;
        out[b * 3 + 1] = o1 * inv;
        out[b * 3 + 2] = o2 * inv;
    }
}

// ---------------- launch --------------------------------------------------
extern "C" void kernel_launch(void* const* d_in, const int* in_sizes, int n_in,
                              void* d_out, int out_size) {
    const float* x  = (const float*)d_in[0];
    const float* W1 = (const float*)d_in[1];
    const float* b1 = (const float*)d_in[2];
    const float* W2 = (const float*)d_in[3];
    const float* b2 = (const float*)d_in[4];
    const float* W3 = (const float*)d_in[5];
    const float* b3 = (const float*)d_in[6];
    const float* W4 = (const float*)d_in[7];
    const float* b4 = (const float*)d_in[8];
    const float* W5 = (const float*)d_in[9];
    const float* b5 = (const float*)d_in[10];
    const float* W6 = (const float*)d_in[11];
    const float* b6 = (const float*)d_in[12];
    float* out = (float*)d_out;

    __half *p_spk1, *p_Wh, *p_Wl;
    float *p_mem2, *p_mem3, *p_mem4, *p_mem5;
    cudaGetSymbolAddress((void**)&p_spk1, g_spk1);
    cudaGetSymbolAddress((void**)&p_Wh, g_Wh);
    cudaGetSymbolAddress((void**)&p_Wl, g_Wl);
    cudaGetSymbolAddress((void**)&p_mem2, g_mem2);
    cudaGetSymbolAddress((void**)&p_mem3, g_mem3);
    cudaGetSymbolAddress((void**)&p_mem4, g_mem4);
    cudaGetSymbolAddress((void**)&p_mem5, g_mem5);

    cudaFuncSetAttribute(k_snn, cudaFuncAttributeMaxDynamicSharedMemorySize, SMEMT);

    k_setup<<<2048, 256>>>(x, W1, b1, W2, W3, W4, W5);
    k_snn<<<NB / 128, 512, SMEMT>>>(p_spk1, p_Wh, p_Wl, b2, b3, b4, b5,
                                    p_mem2, p_mem3, p_mem4, p_mem5,
                                    W6, b6, out);
}